// round 1
// baseline (speedup 1.0000x reference)
#include <cuda_runtime.h>
#include <math.h>

#define Bb 4
#define Cc 64
#define Nn 8192
#define Kk 16
#define Oo 128
#define BN_EPS_F 1e-5f
#define SLOPE 0.2f

// Scratch (allocation-free rule: __device__ globals)
__device__ float g_sq[Bb * Nn];                       // 128 KB
__device__ int   g_idx[Bb * Nn * Kk];                 // 2 MB
__device__ float g_a[(size_t)Bb * Nn * Oo];           // 16 MB: x_j . W1^T * inv
__device__ float g_c[(size_t)Bb * Nn * Oo];           // 16 MB: x_n . (W2-W1)^T * inv + bias

// ---------------------------------------------------------------------------
// Kernel 1: squared norms per point.  x layout (B, C, N) -> coalesced over n.
// ---------------------------------------------------------------------------
__global__ void sq_kernel(const float* __restrict__ x) {
    int b = blockIdx.y;
    int n = blockIdx.x * 256 + threadIdx.x;
    const float* xb = x + (size_t)b * Cc * Nn;
    float s = 0.f;
#pragma unroll
    for (int c = 0; c < Cc; c++) {
        float v = xb[(size_t)c * Nn + n];
        s = fmaf(v, v, s);
    }
    g_sq[b * Nn + n] = s;
}

// ---------------------------------------------------------------------------
// Kernel 2: fused pairwise inner product + top-16 (by 2*inner - sq_j).
// Thread = one query point, 64-dim query in registers, column tiles of 32
// points in shared (broadcast reads), 4 independent accumulator chains.
// ---------------------------------------------------------------------------
__global__ void __launch_bounds__(128, 2) topk_kernel(const float* __restrict__ x) {
    const int b = blockIdx.y;
    const int n = blockIdx.x * 128 + threadIdx.x;
    const float* xb = x + (size_t)b * Cc * Nn;

    float q[Cc];
#pragma unroll
    for (int c = 0; c < Cc; c++) q[c] = xb[(size_t)c * Nn + n];

    float td[Kk];
    int   ti[Kk];
#pragma unroll
    for (int k = 0; k < Kk; k++) { td[k] = -INFINITY; ti[k] = 0; }

    __shared__ float sh[32][68];   // [col_pt][c], pad to dodge STS conflicts, float4-aligned
    __shared__ float ssq[32];

    for (int j0 = 0; j0 < Nn; j0 += 32) {
        __syncthreads();
        for (int idx = threadIdx.x; idx < 32 * Cc; idx += 128) {
            int c = idx >> 5;
            int jj = idx & 31;
            sh[jj][c] = xb[(size_t)c * Nn + j0 + jj];
        }
        if (threadIdx.x < 32) ssq[threadIdx.x] = g_sq[b * Nn + j0 + threadIdx.x];
        __syncthreads();

#pragma unroll 1
        for (int jj = 0; jj < 32; jj += 4) {
            float a0 = 0.f, a1 = 0.f, a2 = 0.f, a3 = 0.f;
#pragma unroll
            for (int c = 0; c < Cc; c += 4) {
                float4 v0 = *(const float4*)&sh[jj + 0][c];
                float4 v1 = *(const float4*)&sh[jj + 1][c];
                float4 v2 = *(const float4*)&sh[jj + 2][c];
                float4 v3 = *(const float4*)&sh[jj + 3][c];
                a0 = fmaf(q[c + 0], v0.x, a0); a1 = fmaf(q[c + 0], v1.x, a1);
                a2 = fmaf(q[c + 0], v2.x, a2); a3 = fmaf(q[c + 0], v3.x, a3);
                a0 = fmaf(q[c + 1], v0.y, a0); a1 = fmaf(q[c + 1], v1.y, a1);
                a2 = fmaf(q[c + 1], v2.y, a2); a3 = fmaf(q[c + 1], v3.y, a3);
                a0 = fmaf(q[c + 2], v0.z, a0); a1 = fmaf(q[c + 2], v1.z, a1);
                a2 = fmaf(q[c + 2], v2.z, a2); a3 = fmaf(q[c + 2], v3.z, a3);
                a0 = fmaf(q[c + 3], v0.w, a0); a1 = fmaf(q[c + 3], v1.w, a1);
                a2 = fmaf(q[c + 3], v2.w, a2); a3 = fmaf(q[c + 3], v3.w, a3);
            }
            float dv[4] = {a0, a1, a2, a3};
#pragma unroll
            for (int u = 0; u < 4; u++) {
                int j = j0 + jj + u;
                float d = fmaf(2.f, dv[u], -ssq[jj + u]);   // rank-equivalent to neg_dist
                if (d > td[Kk - 1] && j != n) {
                    float vd = d;
                    int   vi = j;
#pragma unroll
                    for (int k = 0; k < Kk; k++) {
                        if (vd > td[k]) {
                            float tf = td[k]; td[k] = vd; vd = tf;
                            int   tt = ti[k]; ti[k] = vi; vi = tt;
                        }
                    }
                }
            }
        }
    }
    int base = (b * Nn + n) * Kk;
#pragma unroll
    for (int k = 0; k < Kk; k++) g_idx[base + k] = ti[k];
}

// ---------------------------------------------------------------------------
// Kernel 3: per-point transforms a = x.W1^T * inv ; c = x.(W2-W1)^T * inv + bias
// (BN affine folded in). Thread = one point.
// ---------------------------------------------------------------------------
__global__ void __launch_bounds__(128) pw_kernel(const float* __restrict__ x,
                                                 const float* __restrict__ w,
                                                 const float* __restrict__ gamma,
                                                 const float* __restrict__ beta,
                                                 const float* __restrict__ mean,
                                                 const float* __restrict__ var) {
    int b = blockIdx.y;
    int n = blockIdx.x * 128 + threadIdx.x;
    const float* xb = x + (size_t)b * Cc * Nn;

    float q[Cc];
#pragma unroll
    for (int c = 0; c < Cc; c++) q[c] = xb[(size_t)c * Nn + n];

    __shared__ float w1s[32][Cc + 1];
    __shared__ float wds[32][Cc + 1];
    __shared__ float invs[Oo], biass[Oo];

    {
        int o = threadIdx.x;  // 128 threads cover 128 outputs
        float iv = gamma[o] * rsqrtf(var[o] + BN_EPS_F);
        invs[o] = iv;
        biass[o] = beta[o] - mean[o] * iv;
    }

    size_t obase = (size_t)(b * Nn + n) * Oo;

    for (int oc = 0; oc < Oo; oc += 32) {
        __syncthreads();
        for (int idx = threadIdx.x; idx < 32 * Cc; idx += 128) {
            int o = idx >> 6;
            int c = idx & 63;
            float wa = w[(oc + o) * (2 * Cc) + c];
            float wb = w[(oc + o) * (2 * Cc) + Cc + c];
            w1s[o][c] = wa;
            wds[o][c] = wb - wa;
        }
        __syncthreads();
#pragma unroll 1
        for (int o = 0; o < 32; o += 2) {
            float aa0 = 0.f, ac0 = 0.f, aa1 = 0.f, ac1 = 0.f;
#pragma unroll
            for (int c = 0; c < Cc; c++) {
                aa0 = fmaf(q[c], w1s[o][c], aa0);
                ac0 = fmaf(q[c], wds[o][c], ac0);
                aa1 = fmaf(q[c], w1s[o + 1][c], aa1);
                ac1 = fmaf(q[c], wds[o + 1][c], ac1);
            }
            int oo = oc + o;
            g_a[obase + oo]     = aa0 * invs[oo];
            g_c[obase + oo]     = fmaf(ac0, invs[oo], biass[oo]);
            g_a[obase + oo + 1] = aa1 * invs[oo + 1];
            g_c[obase + oo + 1] = fmaf(ac1, invs[oo + 1], biass[oo + 1]);
        }
    }
}

// ---------------------------------------------------------------------------
// Kernel 4: gather K neighbors' a-rows (L2-resident), add c, LeakyReLU,
// max over k, transpose through SMEM for coalesced (B,O,N) stores.
// Warp = 4 points, lane covers 4 o's via float4.
// ---------------------------------------------------------------------------
__global__ void __launch_bounds__(256) out_kernel(float* __restrict__ out) {
    int b = blockIdx.y;
    int n0 = blockIdx.x * 32;
    int warp = threadIdx.x >> 5;
    int lane = threadIdx.x & 31;

    __shared__ float sh[Oo][33];

#pragma unroll 1
    for (int i = 0; i < 4; i++) {
        int p = warp * 4 + i;
        int n = n0 + p;
        const float4* crow = (const float4*)(g_c + (size_t)(b * Nn + n) * Oo);
        float4 cv = crow[lane];
        float4 m = make_float4(-INFINITY, -INFINITY, -INFINITY, -INFINITY);
        int ib = (b * Nn + n) * Kk;
#pragma unroll
        for (int k = 0; k < Kk; k++) {
            int j = g_idx[ib + k];
            const float4* arow = (const float4*)(g_a + (size_t)(b * Nn + j) * Oo);
            float4 av = arow[lane];
            float y;
            y = av.x + cv.x; y = (y >= 0.f) ? y : SLOPE * y; m.x = fmaxf(m.x, y);
            y = av.y + cv.y; y = (y >= 0.f) ? y : SLOPE * y; m.y = fmaxf(m.y, y);
            y = av.z + cv.z; y = (y >= 0.f) ? y : SLOPE * y; m.z = fmaxf(m.z, y);
            y = av.w + cv.w; y = (y >= 0.f) ? y : SLOPE * y; m.w = fmaxf(m.w, y);
        }
        sh[4 * lane + 0][p] = m.x;
        sh[4 * lane + 1][p] = m.y;
        sh[4 * lane + 2][p] = m.z;
        sh[4 * lane + 3][p] = m.w;
    }
    __syncthreads();
    for (int idx = threadIdx.x; idx < Oo * 32; idx += 256) {
        int o = idx >> 5;
        int p = idx & 31;
        out[((size_t)b * Oo + o) * Nn + n0 + p] = sh[o][p];
    }
}

// ---------------------------------------------------------------------------
extern "C" void kernel_launch(void* const* d_in, const int* in_sizes, int n_in,
                              void* d_out, int out_size) {
    const float* x     = (const float*)d_in[0];
    const float* w     = (const float*)d_in[1];
    const float* gamma = (const float*)d_in[2];
    const float* beta  = (const float*)d_in[3];
    const float* mean  = (const float*)d_in[4];
    const float* var   = (const float*)d_in[5];
    float* out = (float*)d_out;

    sq_kernel<<<dim3(Nn / 256, Bb), 256>>>(x);
    topk_kernel<<<dim3(Nn / 128, Bb), 128>>>(x);
    pw_kernel<<<dim3(Nn / 128, Bb), 128>>>(x, w, gamma, beta, mean, var);
    out_kernel<<<dim3(Nn / 32, Bb), 256>>>(out);
}

// round 5
// speedup vs baseline: 1.1869x; 1.1869x over previous
#include <cuda_runtime.h>
#include <cuda_fp16.h>
#include <math.h>
#include <stdint.h>

#define Bb 4
#define Cc 64
#define Nn 8192
#define Kk 16
#define Oo 128
#define BN_EPS_F 1e-5f
#define SLOPE 0.2f
#define SPLIT_S 2048.0f
#define INV_S (1.0f / 2048.0f)

// -------- scratch (device globals; no allocs allowed) ----------------------
__device__ float g_sq[Bb * Nn];
__device__ int   g_idx[Bb * Nn * Kk];
__device__ float g_a[(size_t)Bb * Nn * Oo];
__device__ float g_c[(size_t)Bb * Nn * Oo];
__device__ __half g_xhi[(size_t)Bb * Nn * Cc];   // (B,N,C) K-major fp16 hi
__device__ __half g_xlo[(size_t)Bb * Nn * Cc];   // fp16((x-hi)*2048)

// -------- helpers -----------------------------------------------------------
__device__ __forceinline__ uint32_t smem_to_u32(const void* p) {
    uint32_t a;
    asm("{ .reg .u64 t; cvta.to.shared.u64 t, %1; cvt.u32.u64 %0, t; }" : "=r"(a) : "l"(p));
    return a;
}
__device__ __forceinline__ void cp16(uint32_t dst, const void* src) {
    asm volatile("cp.async.cg.shared.global [%0], [%1], 16;" :: "r"(dst), "l"(src));
}
#define CP_COMMIT() asm volatile("cp.async.commit_group;" ::: "memory")
#define CP_WAIT(n)  asm volatile("cp.async.wait_group %0;" :: "n"(n) : "memory")

__device__ __forceinline__ void ldsm4(uint32_t* r, uint32_t addr) {
    asm volatile("ldmatrix.sync.aligned.m8n8.x4.shared.b16 {%0,%1,%2,%3}, [%4];"
        : "=r"(r[0]), "=r"(r[1]), "=r"(r[2]), "=r"(r[3]) : "r"(addr));
}
__device__ __forceinline__ void mma16816(float* d, const uint32_t* a, const uint32_t* b) {
    asm volatile(
        "mma.sync.aligned.m16n8k16.row.col.f32.f16.f16.f32 "
        "{%0,%1,%2,%3}, {%4,%5,%6,%7}, {%8,%9}, {%0,%1,%2,%3};"
        : "+f"(d[0]), "+f"(d[1]), "+f"(d[2]), "+f"(d[3])
        : "r"(a[0]), "r"(a[1]), "r"(a[2]), "r"(a[3]), "r"(b[0]), "r"(b[1]));
}

#define INSERT(dm, jj, TD, TI, SELF) do {                                   \
    if ((dm) > TD[15] && (jj) != (SELF)) {                                  \
        float _vd = (dm); int _vi = (jj);                                   \
        _Pragma("unroll")                                                   \
        for (int _k = 0; _k < 16; _k++) {                                   \
            if (_vd > TD[_k]) {                                             \
                float _tf = TD[_k]; TD[_k] = _vd; _vd = _tf;                \
                int _tt = TI[_k]; TI[_k] = _vi; _vi = _tt;                  \
            }                                                               \
        }                                                                   \
    } } while (0)

// SMEM layout (dynamic):
#define SM_A     0         // Ahi 16KB | Alo 16KB
#define SM_B0    32768     // Bhi 32KB | Blo 32KB
#define SM_B1    98304
#define SM_SQ    163840    // 32KB
#define SMEM_TOTAL 196608

// ---------------------------------------------------------------------------
// prep: (B,C,N) fp32 -> (B,N,C) fp16 hi + scaled fp16 lo
// ---------------------------------------------------------------------------
__global__ void prep_kernel(const float* __restrict__ x) {
    __shared__ float t[32][33];
    int b = blockIdx.z;
    int n0 = blockIdx.x * 32, c0 = blockIdx.y * 32;
    int tx = threadIdx.x, ty = threadIdx.y;
#pragma unroll
    for (int i = 0; i < 4; i++)
        t[ty + 8 * i][tx] = x[((size_t)b * Cc + c0 + ty + 8 * i) * Nn + n0 + tx];
    __syncthreads();
#pragma unroll
    for (int i = 0; i < 4; i++) {
        int n = n0 + ty + 8 * i;
        int c = c0 + tx;
        float v = t[tx][ty + 8 * i];
        __half h = __float2half(v);
        float r = (v - __half2float(h)) * SPLIT_S;
        size_t o = (size_t)(b * Nn + n) * Cc + c;
        g_xhi[o] = h;
        g_xlo[o] = __float2half(r);
    }
}

// ---------------------------------------------------------------------------
__global__ void sq_kernel(const float* __restrict__ x) {
    int b = blockIdx.y;
    int n = blockIdx.x * 256 + threadIdx.x;
    const float* xb = x + (size_t)b * Cc * Nn;
    float s = 0.f;
#pragma unroll
    for (int c = 0; c < Cc; c++) {
        float v = xb[(size_t)c * Nn + n];
        s = fmaf(v, v, s);
    }
    g_sq[b * Nn + n] = s;
}

// ---------------------------------------------------------------------------
// topk: mma.sync fp16 scaled-split (hh, hl+lh, ll in separate accumulators)
//       + fused per-row top-16
// ---------------------------------------------------------------------------
__device__ __forceinline__ void load_btile(uint32_t dst, int b, int brow0) {
    const char* sh_ = (const char*)(g_xhi + (size_t)(b * Nn + brow0) * Cc);
    const char* sl_ = (const char*)(g_xlo + (size_t)(b * Nn + brow0) * Cc);
    int tid = threadIdx.x;
#pragma unroll
    for (int m = 0; m < 8; m++) {
        int idx = m * 256 + tid;                 // 0..2047 = 256 rows x 8 chunks
        uint32_t off = (uint32_t)idx * 16;
        uint32_t sw = off ^ ((off >> 3) & 0x70);
        cp16(dst + sw, sh_ + off);
        cp16(dst + 32768 + sw, sl_ + off);
    }
}

__global__ void __launch_bounds__(256, 1) topk_kernel() {
    extern __shared__ char smem[];
    const uint32_t sb = smem_to_u32(smem);
    const int tid = threadIdx.x;
    const int wid = tid >> 5;
    const int lane = tid & 31;
    const int b = blockIdx.y;
    const int qn0 = blockIdx.x * 128;
    float* s_sq = (float*)(smem + SM_SQ);

    for (int i = tid; i < Nn; i += 256) s_sq[i] = g_sq[b * Nn + i];

    // ---- prologue: A tile, B tile 0 ----
    {
        const char* sh_ = (const char*)(g_xhi + (size_t)(b * Nn + qn0) * Cc);
        const char* sl_ = (const char*)(g_xlo + (size_t)(b * Nn + qn0) * Cc);
#pragma unroll
        for (int m = 0; m < 4; m++) {
            int idx = m * 256 + tid;             // 0..1023 = 128 rows x 8 chunks
            uint32_t off = (uint32_t)idx * 16;
            uint32_t sw = off ^ ((off >> 3) & 0x70);
            cp16(sb + SM_A + sw, sh_ + off);
            cp16(sb + SM_A + 16384 + sw, sl_ + off);
        }
    }
    CP_COMMIT();
    load_btile(sb + SM_B0, b, 0);
    CP_COMMIT();

    CP_WAIT(1);           // A ready
    __syncthreads();

    // ---- A fragments, resident all kernel ----
    const int rbase = wid << 4;
    uint32_t afh[4][4], afl[4][4];
    {
        uint32_t rowAoff = (uint32_t)(rbase + (lane & 15)) * 128;
        int kofA = ((lane >> 4) & 1) * 16;
#pragma unroll
        for (int s = 0; s < 4; s++) {
            uint32_t kx = (uint32_t)((s * 32 + kofA) ^ ((lane & 7) * 16));
            ldsm4(afh[s], sb + SM_A + rowAoff + kx);
            ldsm4(afl[s], sb + SM_A + 16384 + rowAoff + kx);
        }
    }

    // B ldmatrix lane addressing (constant per lane)
    const int nrl = (lane & 7) + ((lane >> 4) << 3);   // 0..15
    const uint32_t browoff = (uint32_t)nrl * 128;
    const int kofB = ((lane >> 3) & 1) * 16;
    uint32_t kxB[4];
#pragma unroll
    for (int s = 0; s < 4; s++)
        kxB[s] = (uint32_t)((s * 32 + kofB) ^ ((lane & 7) * 16));

    float td0[16], td1[16];
    int   ti0[16], ti1[16];
#pragma unroll
    for (int k = 0; k < 16; k++) {
        td0[k] = -INFINITY; td1[k] = -INFINITY; ti0[k] = 0; ti1[k] = 0;
    }
    const int r0g = qn0 + rbase + (lane >> 2);
    const int r1g = r0g + 8;

#pragma unroll 1
    for (int t = 0; t < 32; t++) {
        const int buf = t & 1;
        if (t + 1 < 32) {
            load_btile(sb + (buf ? SM_B0 : SM_B1), b, (t + 1) * 256);
            CP_COMMIT();
            CP_WAIT(1);
        } else {
            CP_WAIT(0);
        }
        __syncthreads();

        const uint32_t bh_base = sb + (buf ? SM_B1 : SM_B0);
        const uint32_t bl_base = bh_base + 32768;

#pragma unroll 1
        for (int g = 0; g < 8; g++) {           // 8 groups of 32 columns
            // 3 scale-separated accumulator sets x 4 col-subtiles
            float hA0[4] = {0,0,0,0}, hA1[4] = {0,0,0,0}, hA2[4] = {0,0,0,0}, hA3[4] = {0,0,0,0};
            float mA0[4] = {0,0,0,0}, mA1[4] = {0,0,0,0}, mA2[4] = {0,0,0,0}, mA3[4] = {0,0,0,0};
            float lA0[4] = {0,0,0,0}, lA1[4] = {0,0,0,0}, lA2[4] = {0,0,0,0}, lA3[4] = {0,0,0,0};
#pragma unroll
            for (int s = 0; s < 4; s++) {
                uint32_t bh0[4], bh1[4], bl0[4], bl1[4];
                uint32_t bo = g * 4096 + browoff + kxB[s];
                ldsm4(bh0, bh_base + bo);
                ldsm4(bh1, bh_base + bo + 2048);
                ldsm4(bl0, bl_base + bo);
                ldsm4(bl1, bl_base + bo + 2048);
                // hh -> hA (scale 1)
                mma16816(hA0, afh[s], bh0 + 0); mma16816(hA1, afh[s], bh0 + 2);
                mma16816(hA2, afh[s], bh1 + 0); mma16816(hA3, afh[s], bh1 + 2);
                // hl + lh -> mA (scale 1/S)
                mma16816(mA0, afh[s], bl0 + 0); mma16816(mA1, afh[s], bl0 + 2);
                mma16816(mA2, afh[s], bl1 + 0); mma16816(mA3, afh[s], bl1 + 2);
                mma16816(mA0, afl[s], bh0 + 0); mma16816(mA1, afl[s], bh0 + 2);
                mma16816(mA2, afl[s], bh1 + 0); mma16816(mA3, afl[s], bh1 + 2);
                // ll -> lA (scale 1/S^2)
                mma16816(lA0, afl[s], bl0 + 0); mma16816(lA1, afl[s], bl0 + 2);
                mma16816(lA2, afl[s], bl1 + 0); mma16816(lA3, afl[s], bl1 + 2);
            }
            const int jb = t * 256 + g * 32 + ((lane & 3) << 1);
            float2 sq0 = *(const float2*)&s_sq[jb];
            float2 sq1 = *(const float2*)&s_sq[jb + 8];
            float2 sq2 = *(const float2*)&s_sq[jb + 16];
            float2 sq3 = *(const float2*)&s_sq[jb + 24];
#define COMB(H, M, L) fmaf(fmaf((L), INV_S, (M)), INV_S, (H))
            float d;
            d = fmaf(2.f, COMB(hA0[0], mA0[0], lA0[0]), -sq0.x); INSERT(d, jb,      td0, ti0, r0g);
            d = fmaf(2.f, COMB(hA0[1], mA0[1], lA0[1]), -sq0.y); INSERT(d, jb + 1,  td0, ti0, r0g);
            d = fmaf(2.f, COMB(hA0[2], mA0[2], lA0[2]), -sq0.x); INSERT(d, jb,      td1, ti1, r1g);
            d = fmaf(2.f, COMB(hA0[3], mA0[3], lA0[3]), -sq0.y); INSERT(d, jb + 1,  td1, ti1, r1g);
            d = fmaf(2.f, COMB(hA1[0], mA1[0], lA1[0]), -sq1.x); INSERT(d, jb + 8,  td0, ti0, r0g);
            d = fmaf(2.f, COMB(hA1[1], mA1[1], lA1[1]), -sq1.y); INSERT(d, jb + 9,  td0, ti0, r0g);
            d = fmaf(2.f, COMB(hA1[2], mA1[2], lA1[2]), -sq1.x); INSERT(d, jb + 8,  td1, ti1, r1g);
            d = fmaf(2.f, COMB(hA1[3], mA1[3], lA1[3]), -sq1.y); INSERT(d, jb + 9,  td1, ti1, r1g);
            d = fmaf(2.f, COMB(hA2[0], mA2[0], lA2[0]), -sq2.x); INSERT(d, jb + 16, td0, ti0, r0g);
            d = fmaf(2.f, COMB(hA2[1], mA2[1], lA2[1]), -sq2.y); INSERT(d, jb + 17, td0, ti0, r0g);
            d = fmaf(2.f, COMB(hA2[2], mA2[2], lA2[2]), -sq2.x); INSERT(d, jb + 16, td1, ti1, r1g);
            d = fmaf(2.f, COMB(hA2[3], mA2[3], lA2[3]), -sq2.y); INSERT(d, jb + 17, td1, ti1, r1g);
            d = fmaf(2.f, COMB(hA3[0], mA3[0], lA3[0]), -sq3.x); INSERT(d, jb + 24, td0, ti0, r0g);
            d = fmaf(2.f, COMB(hA3[1], mA3[1], lA3[1]), -sq3.y); INSERT(d, jb + 25, td0, ti0, r0g);
            d = fmaf(2.f, COMB(hA3[2], mA3[2], lA3[2]), -sq3.x); INSERT(d, jb + 24, td1, ti1, r1g);
            d = fmaf(2.f, COMB(hA3[3], mA3[3], lA3[3]), -sq3.y); INSERT(d, jb + 25, td1, ti1, r1g);
#undef COMB
        }
        __syncthreads();
    }

    // ---- merge the 4 column-partitions of each row (reuse B0 SMEM) ----
    float* cv = (float*)(smem + SM_B0);            // [128][4][16] floats
    int*   ci = (int*)(smem + SM_B0 + 32768);      // [128][4][16] ints
    {
        int r0l = rbase + (lane >> 2);
        int q = lane & 3;
#pragma unroll
        for (int k = 0; k < 16; k++) {
            cv[(r0l * 4 + q) * 16 + k] = td0[k];
            ci[(r0l * 4 + q) * 16 + k] = ti0[k];
            cv[((r0l + 8) * 4 + q) * 16 + k] = td1[k];
            ci[((r0l + 8) * 4 + q) * 16 + k] = ti1[k];
        }
    }
    __syncthreads();

    if (tid < 128) {
        float td[16]; int ti[16];
#pragma unroll
        for (int k = 0; k < 16; k++) { td[k] = -INFINITY; ti[k] = 0; }
#pragma unroll 1
        for (int q = 0; q < 4; q++) {
#pragma unroll
            for (int k = 0; k < 16; k++) {
                float v = cv[(tid * 4 + q) * 16 + k];
                int j = ci[(tid * 4 + q) * 16 + k];
                if (v > td[15]) {
                    float vd = v; int vi = j;
#pragma unroll
                    for (int kk = 0; kk < 16; kk++) {
                        if (vd > td[kk]) {
                            float tf = td[kk]; td[kk] = vd; vd = tf;
                            int tt = ti[kk]; ti[kk] = vi; vi = tt;
                        }
                    }
                }
            }
        }
        int base = (b * Nn + qn0 + tid) * Kk;
#pragma unroll
        for (int k = 0; k < 16; k++) g_idx[base + k] = ti[k];
    }
}

// ---------------------------------------------------------------------------
// pw: a = x.W1^T * inv ; c = x.(W2-W1)^T * inv + bias   (BN folded)
// ---------------------------------------------------------------------------
__global__ void __launch_bounds__(128) pw_kernel(const float* __restrict__ x,
                                                 const float* __restrict__ w,
                                                 const float* __restrict__ gamma,
                                                 const float* __restrict__ beta,
                                                 const float* __restrict__ mean,
                                                 const float* __restrict__ var) {
    int b = blockIdx.y;
    int n = blockIdx.x * 128 + threadIdx.x;
    const float* xb = x + (size_t)b * Cc * Nn;

    float q[Cc];
#pragma unroll
    for (int c = 0; c < Cc; c++) q[c] = xb[(size_t)c * Nn + n];

    __shared__ float w1s[32][Cc + 1];
    __shared__ float wds[32][Cc + 1];
    __shared__ float invs[Oo], biass[Oo];

    {
        int o = threadIdx.x;
        float iv = gamma[o] * rsqrtf(var[o] + BN_EPS_F);
        invs[o] = iv;
        biass[o] = beta[o] - mean[o] * iv;
    }

    size_t obase = (size_t)(b * Nn + n) * Oo;

    for (int oc = 0; oc < Oo; oc += 32) {
        __syncthreads();
        for (int idx = threadIdx.x; idx < 32 * Cc; idx += 128) {
            int o = idx >> 6;
            int c = idx & 63;
            float wa = w[(oc + o) * (2 * Cc) + c];
            float wb = w[(oc + o) * (2 * Cc) + Cc + c];
            w1s[o][c] = wa;
            wds[o][c] = wb - wa;
        }
        __syncthreads();
#pragma unroll 1
        for (int o = 0; o < 32; o += 2) {
            float aa0 = 0.f, ac0 = 0.f, aa1 = 0.f, ac1 = 0.f;
#pragma unroll
            for (int c = 0; c < Cc; c++) {
                aa0 = fmaf(q[c], w1s[o][c], aa0);
                ac0 = fmaf(q[c], wds[o][c], ac0);
                aa1 = fmaf(q[c], w1s[o + 1][c], aa1);
                ac1 = fmaf(q[c], wds[o + 1][c], ac1);
            }
            int oo = oc + o;
            g_a[obase + oo]     = aa0 * invs[oo];
            g_c[obase + oo]     = fmaf(ac0, invs[oo], biass[oo]);
            g_a[obase + oo + 1] = aa1 * invs[oo + 1];
            g_c[obase + oo + 1] = fmaf(ac1, invs[oo + 1], biass[oo + 1]);
        }
    }
}

// ---------------------------------------------------------------------------
// out: gather K neighbor a-rows, +c, LeakyReLU, max over k, transposed store
// ---------------------------------------------------------------------------
__global__ void __launch_bounds__(256) out_kernel(float* __restrict__ out) {
    int b = blockIdx.y;
    int n0 = blockIdx.x * 32;
    int warp = threadIdx.x >> 5;
    int lane = threadIdx.x & 31;

    __shared__ float sh[Oo][33];

#pragma unroll 1
    for (int i = 0; i < 4; i++) {
        int p = warp * 4 + i;
        int n = n0 + p;
        const float4* crow = (const float4*)(g_c + (size_t)(b * Nn + n) * Oo);
        float4 cv = crow[lane];
        float4 m = make_float4(-INFINITY, -INFINITY, -INFINITY, -INFINITY);
        int ib = (b * Nn + n) * Kk;
#pragma unroll
        for (int k = 0; k < Kk; k++) {
            int j = g_idx[ib + k];
            const float4* arow = (const float4*)(g_a + (size_t)(b * Nn + j) * Oo);
            float4 av = arow[lane];
            float y;
            y = av.x + cv.x; y = (y >= 0.f) ? y : SLOPE * y; m.x = fmaxf(m.x, y);
            y = av.y + cv.y; y = (y >= 0.f) ? y : SLOPE * y; m.y = fmaxf(m.y, y);
            y = av.z + cv.z; y = (y >= 0.f) ? y : SLOPE * y; m.z = fmaxf(m.z, y);
            y = av.w + cv.w; y = (y >= 0.f) ? y : SLOPE * y; m.w = fmaxf(m.w, y);
        }
        sh[4 * lane + 0][p] = m.x;
        sh[4 * lane + 1][p] = m.y;
        sh[4 * lane + 2][p] = m.z;
        sh[4 * lane + 3][p] = m.w;
    }
    __syncthreads();
    for (int idx = threadIdx.x; idx < Oo * 32; idx += 256) {
        int o = idx >> 5;
        int p = idx & 31;
        out[((size_t)b * Oo + o) * Nn + n0 + p] = sh[o][p];
    }
}

// ---------------------------------------------------------------------------
extern "C" void kernel_launch(void* const* d_in, const int* in_sizes, int n_in,
                              void* d_out, int out_size) {
    const float* x     = (const float*)d_in[0];
    const float* w     = (const float*)d_in[1];
    const float* gamma = (const float*)d_in[2];
    const float* beta  = (const float*)d_in[3];
    const float* mean  = (const float*)d_in[4];
    const float* var   = (const float*)d_in[5];
    float* out = (float*)d_out;

    prep_kernel<<<dim3(Nn / 32, Cc / 32, Bb), dim3(32, 8)>>>(x);
    sq_kernel<<<dim3(Nn / 256, Bb), 256>>>(x);

    static int smem_set = 0;
    if (!smem_set) {
        cudaFuncSetAttribute(topk_kernel, cudaFuncAttributeMaxDynamicSharedMemorySize, SMEM_TOTAL);
        smem_set = 1;
    }
    topk_kernel<<<dim3(Nn / 128, Bb), 256, SMEM_TOTAL>>>();

    pw_kernel<<<dim3(Nn / 128, Bb), 128>>>(x, w, gamma, beta, mean, var);
    out_kernel<<<dim3(Nn / 32, Bb), 256>>>(out);
}

// round 6
// speedup vs baseline: 1.2506x; 1.0537x over previous
#include <cuda_runtime.h>
#include <cuda_fp16.h>
#include <math.h>
#include <stdint.h>

#define Bb 4
#define Cc 64
#define Nn 8192
#define Kk 16
#define Oo 128
#define Mm 24            // hh-filter candidate count
#define BN_EPS_F 1e-5f
#define SLOPE 0.2f

// -------- scratch (device globals; no allocs allowed) ----------------------
__device__ float g_sq[Bb * Nn];
__device__ int   g_idx[Bb * Nn * Kk];
__device__ int   g_cand[Bb * Nn * Mm];
__device__ float g_a[(size_t)Bb * Nn * Oo];
__device__ float g_c[(size_t)Bb * Nn * Oo];
__device__ __half g_xhi[(size_t)Bb * Nn * Cc];   // (B,N,C) K-major fp16
__device__ float  g_xt[(size_t)Bb * Nn * Cc];    // (B,N,C) fp32 for exact rescore

// -------- helpers -----------------------------------------------------------
__device__ __forceinline__ uint32_t smem_to_u32(const void* p) {
    uint32_t a;
    asm("{ .reg .u64 t; cvta.to.shared.u64 t, %1; cvt.u32.u64 %0, t; }" : "=r"(a) : "l"(p));
    return a;
}
__device__ __forceinline__ void cp16(uint32_t dst, const void* src) {
    asm volatile("cp.async.cg.shared.global [%0], [%1], 16;" :: "r"(dst), "l"(src));
}
#define CP_COMMIT() asm volatile("cp.async.commit_group;" ::: "memory")
#define CP_WAIT(n)  asm volatile("cp.async.wait_group %0;" :: "n"(n) : "memory")

__device__ __forceinline__ void ldsm4(uint32_t* r, uint32_t addr) {
    asm volatile("ldmatrix.sync.aligned.m8n8.x4.shared.b16 {%0,%1,%2,%3}, [%4];"
        : "=r"(r[0]), "=r"(r[1]), "=r"(r[2]), "=r"(r[3]) : "r"(addr));
}
__device__ __forceinline__ void mma16816(float* d, const uint32_t* a, const uint32_t* b) {
    asm volatile(
        "mma.sync.aligned.m16n8k16.row.col.f32.f16.f16.f32 "
        "{%0,%1,%2,%3}, {%4,%5,%6,%7}, {%8,%9}, {%0,%1,%2,%3};"
        : "+f"(d[0]), "+f"(d[1]), "+f"(d[2]), "+f"(d[3])
        : "r"(a[0]), "r"(a[1]), "r"(a[2]), "r"(a[3]), "r"(b[0]), "r"(b[1]));
}

#define INSERT(dm, jj, TD, TI, SELF) do {                                   \
    if ((dm) > TD[15] && (jj) != (SELF)) {                                  \
        float _vd = (dm); int _vi = (jj);                                   \
        _Pragma("unroll")                                                   \
        for (int _k = 0; _k < 16; _k++) {                                   \
            if (_vd > TD[_k]) {                                             \
                float _tf = TD[_k]; TD[_k] = _vd; _vd = _tf;                \
                int _tt = TI[_k]; TI[_k] = _vi; _vi = _tt;                  \
            }                                                               \
        }                                                                   \
    } } while (0)

// SMEM layout (dynamic):
#define SM_A     0          // A hi 16KB
#define SM_B0    16384      // B hi 32KB
#define SM_B1    49152      // B hi 32KB
#define SM_SQ    81920      // 32KB
#define SMEM_TOTAL 114688

// ---------------------------------------------------------------------------
// prep: (B,C,N) fp32 -> (B,N,C) fp16 hi  +  (B,N,C) fp32 copy
// ---------------------------------------------------------------------------
__global__ void prep_kernel(const float* __restrict__ x) {
    __shared__ float t[32][33];
    int b = blockIdx.z;
    int n0 = blockIdx.x * 32, c0 = blockIdx.y * 32;
    int tx = threadIdx.x, ty = threadIdx.y;
#pragma unroll
    for (int i = 0; i < 4; i++)
        t[ty + 8 * i][tx] = x[((size_t)b * Cc + c0 + ty + 8 * i) * Nn + n0 + tx];
    __syncthreads();
#pragma unroll
    for (int i = 0; i < 4; i++) {
        int n = n0 + ty + 8 * i;
        int c = c0 + tx;
        float v = t[tx][ty + 8 * i];
        size_t o = (size_t)(b * Nn + n) * Cc + c;
        g_xhi[o] = __float2half(v);
        g_xt[o] = v;
    }
}

// ---------------------------------------------------------------------------
__global__ void sq_kernel(const float* __restrict__ x) {
    int b = blockIdx.y;
    int n = blockIdx.x * 256 + threadIdx.x;
    const float* xb = x + (size_t)b * Cc * Nn;
    float s = 0.f;
#pragma unroll
    for (int c = 0; c < Cc; c++) {
        float v = xb[(size_t)c * Nn + n];
        s = fmaf(v, v, s);
    }
    g_sq[b * Nn + n] = s;
}

// ---------------------------------------------------------------------------
// Pass 1: hh-only mma.sync distances + per-row top-24 candidate filter
// ---------------------------------------------------------------------------
__device__ __forceinline__ void load_btile(uint32_t dst, int b, int brow0) {
    const char* sh_ = (const char*)(g_xhi + (size_t)(b * Nn + brow0) * Cc);
    int tid = threadIdx.x;
#pragma unroll
    for (int m = 0; m < 8; m++) {
        int idx = m * 256 + tid;                 // 0..2047 = 256 rows x 8 chunks
        uint32_t off = (uint32_t)idx * 16;
        uint32_t sw = off ^ ((off >> 3) & 0x70);
        cp16(dst + sw, sh_ + off);
    }
}

__global__ void __launch_bounds__(256) topk1_kernel() {
    extern __shared__ char smem[];
    const uint32_t sb = smem_to_u32(smem);
    const int tid = threadIdx.x;
    const int wid = tid >> 5;
    const int lane = tid & 31;
    const int b = blockIdx.y;
    const int qn0 = blockIdx.x * 128;
    float* s_sq = (float*)(smem + SM_SQ);

    for (int i = tid; i < Nn; i += 256) s_sq[i] = g_sq[b * Nn + i];

    {   // A tile (fp16 hi, 128 rows)
        const char* sh_ = (const char*)(g_xhi + (size_t)(b * Nn + qn0) * Cc);
#pragma unroll
        for (int m = 0; m < 4; m++) {
            int idx = m * 256 + tid;
            uint32_t off = (uint32_t)idx * 16;
            uint32_t sw = off ^ ((off >> 3) & 0x70);
            cp16(sb + SM_A + sw, sh_ + off);
        }
    }
    CP_COMMIT();
    load_btile(sb + SM_B0, b, 0);
    CP_COMMIT();

    CP_WAIT(1);           // A ready
    __syncthreads();

    // A fragments resident in registers
    const int rbase = wid << 4;
    uint32_t afh[4][4];
    {
        uint32_t rowAoff = (uint32_t)(rbase + (lane & 15)) * 128;
        int kofA = ((lane >> 4) & 1) * 16;
#pragma unroll
        for (int s = 0; s < 4; s++) {
            uint32_t kx = (uint32_t)((s * 32 + kofA) ^ ((lane & 7) * 16));
            ldsm4(afh[s], sb + SM_A + rowAoff + kx);
        }
    }

    const int nrl = (lane & 7) + ((lane >> 4) << 3);   // 0..15
    const uint32_t browoff = (uint32_t)nrl * 128;
    const int kofB = ((lane >> 3) & 1) * 16;
    uint32_t kxB[4];
#pragma unroll
    for (int s = 0; s < 4; s++)
        kxB[s] = (uint32_t)((s * 32 + kofB) ^ ((lane & 7) * 16));

    float td0[16], td1[16];
    int   ti0[16], ti1[16];
#pragma unroll
    for (int k = 0; k < 16; k++) {
        td0[k] = -INFINITY; td1[k] = -INFINITY; ti0[k] = 0; ti1[k] = 0;
    }
    const int r0g = qn0 + rbase + (lane >> 2);
    const int r1g = r0g + 8;

#pragma unroll 1
    for (int t = 0; t < 32; t++) {
        const int buf = t & 1;
        if (t + 1 < 32) {
            load_btile(sb + (buf ? SM_B0 : SM_B1), b, (t + 1) * 256);
            CP_COMMIT();
            CP_WAIT(1);
        } else {
            CP_WAIT(0);
        }
        __syncthreads();

        const uint32_t bh_base = sb + (buf ? SM_B1 : SM_B0);

#pragma unroll 1
        for (int g = 0; g < 8; g++) {           // 8 groups of 32 columns
            float a0[4] = {0,0,0,0}, a1[4] = {0,0,0,0};
            float a2[4] = {0,0,0,0}, a3[4] = {0,0,0,0};
#pragma unroll
            for (int s = 0; s < 4; s++) {
                uint32_t bh0[4], bh1[4];
                uint32_t bo = g * 4096 + browoff + kxB[s];
                ldsm4(bh0, bh_base + bo);
                ldsm4(bh1, bh_base + bo + 2048);
                mma16816(a0, afh[s], bh0 + 0); mma16816(a1, afh[s], bh0 + 2);
                mma16816(a2, afh[s], bh1 + 0); mma16816(a3, afh[s], bh1 + 2);
            }
            const int jb = t * 256 + g * 32 + ((lane & 3) << 1);
            float2 sq0 = *(const float2*)&s_sq[jb];
            float2 sq1 = *(const float2*)&s_sq[jb + 8];
            float2 sq2 = *(const float2*)&s_sq[jb + 16];
            float2 sq3 = *(const float2*)&s_sq[jb + 24];
            float d;
            d = fmaf(2.f, a0[0], -sq0.x); INSERT(d, jb,      td0, ti0, r0g);
            d = fmaf(2.f, a0[1], -sq0.y); INSERT(d, jb + 1,  td0, ti0, r0g);
            d = fmaf(2.f, a0[2], -sq0.x); INSERT(d, jb,      td1, ti1, r1g);
            d = fmaf(2.f, a0[3], -sq0.y); INSERT(d, jb + 1,  td1, ti1, r1g);
            d = fmaf(2.f, a1[0], -sq1.x); INSERT(d, jb + 8,  td0, ti0, r0g);
            d = fmaf(2.f, a1[1], -sq1.y); INSERT(d, jb + 9,  td0, ti0, r0g);
            d = fmaf(2.f, a1[2], -sq1.x); INSERT(d, jb + 8,  td1, ti1, r1g);
            d = fmaf(2.f, a1[3], -sq1.y); INSERT(d, jb + 9,  td1, ti1, r1g);
            d = fmaf(2.f, a2[0], -sq2.x); INSERT(d, jb + 16, td0, ti0, r0g);
            d = fmaf(2.f, a2[1], -sq2.y); INSERT(d, jb + 17, td0, ti0, r0g);
            d = fmaf(2.f, a2[2], -sq2.x); INSERT(d, jb + 16, td1, ti1, r1g);
            d = fmaf(2.f, a2[3], -sq2.y); INSERT(d, jb + 17, td1, ti1, r1g);
            d = fmaf(2.f, a3[0], -sq3.x); INSERT(d, jb + 24, td0, ti0, r0g);
            d = fmaf(2.f, a3[1], -sq3.y); INSERT(d, jb + 25, td0, ti0, r0g);
            d = fmaf(2.f, a3[2], -sq3.x); INSERT(d, jb + 24, td1, ti1, r1g);
            d = fmaf(2.f, a3[3], -sq3.y); INSERT(d, jb + 25, td1, ti1, r1g);
        }
        __syncthreads();
    }

    // ---- merge 4 column-partitions per row -> top-24 candidates ----
    float* cv = (float*)(smem + SM_B0);            // [128][4][16] floats (32KB)
    int*   ci = (int*)(smem + SM_B0 + 32768);      // [128][4][16] ints (32KB, fits B1+)
    {
        int r0l = rbase + (lane >> 2);
        int q = lane & 3;
#pragma unroll
        for (int k = 0; k < 16; k++) {
            cv[(r0l * 4 + q) * 16 + k] = td0[k];
            ci[(r0l * 4 + q) * 16 + k] = ti0[k];
            cv[((r0l + 8) * 4 + q) * 16 + k] = td1[k];
            ci[((r0l + 8) * 4 + q) * 16 + k] = ti1[k];
        }
    }
    __syncthreads();

    if (tid < 128) {
        float td[Mm]; int ti[Mm];
#pragma unroll
        for (int k = 0; k < Mm; k++) { td[k] = -INFINITY; ti[k] = 0; }
#pragma unroll 1
        for (int q = 0; q < 4; q++) {
#pragma unroll
            for (int k = 0; k < 16; k++) {
                float v = cv[(tid * 4 + q) * 16 + k];
                int j = ci[(tid * 4 + q) * 16 + k];
                if (v > td[Mm - 1]) {
                    float vd = v; int vi = j;
#pragma unroll
                    for (int kk = 0; kk < Mm; kk++) {
                        if (vd > td[kk]) {
                            float tf = td[kk]; td[kk] = vd; vd = tf;
                            int tt = ti[kk]; ti[kk] = vi; vi = tt;
                        }
                    }
                }
            }
        }
        int base = (b * Nn + qn0 + tid) * Mm;
#pragma unroll
        for (int k = 0; k < Mm; k++) g_cand[base + k] = ti[k];
    }
}

// ---------------------------------------------------------------------------
// Pass 2: exact fp32 rescore of 24 candidates, select true top-16
// warp = one row, lane = one candidate
// ---------------------------------------------------------------------------
__global__ void __launch_bounds__(256) rescore_kernel() {
    int b = blockIdx.y;
    int warp = threadIdx.x >> 5;
    int lane = threadIdx.x & 31;
    int n = blockIdx.x * 8 + warp;
    int rowbase = b * Nn + n;

    float d = -INFINITY;
    int j = 0;
    if (lane < Mm) j = g_cand[rowbase * Mm + lane];

    const float4* q4 = (const float4*)(g_xt + (size_t)rowbase * Cc);
    if (lane < Mm) {
        const float4* c4 = (const float4*)(g_xt + (size_t)(b * Nn + j) * Cc);
        float acc = 0.f;
#pragma unroll
        for (int i = 0; i < 16; i++) {
            float4 qv = q4[i];
            float4 cvv = c4[i];
            acc = fmaf(qv.x, cvv.x, acc);
            acc = fmaf(qv.y, cvv.y, acc);
            acc = fmaf(qv.z, cvv.z, acc);
            acc = fmaf(qv.w, cvv.w, acc);
        }
        d = fmaf(2.f, acc, -g_sq[b * Nn + j]);
    }

    int base = rowbase * Kk;
#pragma unroll 1
    for (int k = 0; k < Kk; k++) {
        float bm = d; int bi = lane;
#pragma unroll
        for (int off = 16; off; off >>= 1) {
            float od = __shfl_down_sync(0xffffffff, bm, off);
            int   oi = __shfl_down_sync(0xffffffff, bi, off);
            if (od > bm) { bm = od; bi = oi; }
        }
        bi = __shfl_sync(0xffffffff, bi, 0);
        if (lane == bi) { g_idx[base + k] = j; d = -INFINITY; }
    }
}

// ---------------------------------------------------------------------------
// pw: a = x.W1^T * inv ; c = x.(W2-W1)^T * inv + bias   (BN folded)
// z-dim splits output channels for 2x occupancy
// ---------------------------------------------------------------------------
__global__ void __launch_bounds__(128) pw_kernel(const float* __restrict__ x,
                                                 const float* __restrict__ w,
                                                 const float* __restrict__ gamma,
                                                 const float* __restrict__ beta,
                                                 const float* __restrict__ mean,
                                                 const float* __restrict__ var) {
    int b = blockIdx.y;
    int zz = blockIdx.z;
    int n = blockIdx.x * 128 + threadIdx.x;
    const float* xb = x + (size_t)b * Cc * Nn;

    float q[Cc];
#pragma unroll
    for (int c = 0; c < Cc; c++) q[c] = xb[(size_t)c * Nn + n];

    __shared__ float w1s[32][Cc + 1];
    __shared__ float wds[32][Cc + 1];
    __shared__ float invs[Oo], biass[Oo];

    {
        int o = threadIdx.x;
        float iv = gamma[o] * rsqrtf(var[o] + BN_EPS_F);
        invs[o] = iv;
        biass[o] = beta[o] - mean[o] * iv;
    }

    size_t obase = (size_t)(b * Nn + n) * Oo;

    for (int oc = 64 * zz; oc < 64 * zz + 64; oc += 32) {
        __syncthreads();
        for (int idx = threadIdx.x; idx < 32 * Cc; idx += 128) {
            int o = idx >> 6;
            int c = idx & 63;
            float wa = w[(oc + o) * (2 * Cc) + c];
            float wb = w[(oc + o) * (2 * Cc) + Cc + c];
            w1s[o][c] = wa;
            wds[o][c] = wb - wa;
        }
        __syncthreads();
#pragma unroll 1
        for (int o = 0; o < 32; o += 2) {
            float aa0 = 0.f, ac0 = 0.f, aa1 = 0.f, ac1 = 0.f;
#pragma unroll
            for (int c = 0; c < Cc; c++) {
                aa0 = fmaf(q[c], w1s[o][c], aa0);
                ac0 = fmaf(q[c], wds[o][c], ac0);
                aa1 = fmaf(q[c], w1s[o + 1][c], aa1);
                ac1 = fmaf(q[c], wds[o + 1][c], ac1);
            }
            int oo = oc + o;
            g_a[obase + oo]     = aa0 * invs[oo];
            g_c[obase + oo]     = fmaf(ac0, invs[oo], biass[oo]);
            g_a[obase + oo + 1] = aa1 * invs[oo + 1];
            g_c[obase + oo + 1] = fmaf(ac1, invs[oo + 1], biass[oo + 1]);
        }
    }
}

// ---------------------------------------------------------------------------
// out: gather K neighbor a-rows, +c, LeakyReLU, max over k, transposed store
// ---------------------------------------------------------------------------
__global__ void __launch_bounds__(256) out_kernel(float* __restrict__ out) {
    int b = blockIdx.y;
    int n0 = blockIdx.x * 32;
    int warp = threadIdx.x >> 5;
    int lane = threadIdx.x & 31;

    __shared__ float sh[Oo][33];

#pragma unroll 1
    for (int i = 0; i < 4; i++) {
        int p = warp * 4 + i;
        int n = n0 + p;
        const float4* crow = (const float4*)(g_c + (size_t)(b * Nn + n) * Oo);
        float4 cv = crow[lane];
        float4 m = make_float4(-INFINITY, -INFINITY, -INFINITY, -INFINITY);
        int ib = (b * Nn + n) * Kk;
#pragma unroll
        for (int k = 0; k < Kk; k++) {
            int j = g_idx[ib + k];
            const float4* arow = (const float4*)(g_a + (size_t)(b * Nn + j) * Oo);
            float4 av = arow[lane];
            float y;
            y = av.x + cv.x; y = (y >= 0.f) ? y : SLOPE * y; m.x = fmaxf(m.x, y);
            y = av.y + cv.y; y = (y >= 0.f) ? y : SLOPE * y; m.y = fmaxf(m.y, y);
            y = av.z + cv.z; y = (y >= 0.f) ? y : SLOPE * y; m.z = fmaxf(m.z, y);
            y = av.w + cv.w; y = (y >= 0.f) ? y : SLOPE * y; m.w = fmaxf(m.w, y);
        }
        sh[4 * lane + 0][p] = m.x;
        sh[4 * lane + 1][p] = m.y;
        sh[4 * lane + 2][p] = m.z;
        sh[4 * lane + 3][p] = m.w;
    }
    __syncthreads();
    for (int idx = threadIdx.x; idx < Oo * 32; idx += 256) {
        int o = idx >> 5;
        int p = idx & 31;
        out[((size_t)b * Oo + o) * Nn + n0 + p] = sh[o][p];
    }
}

// ---------------------------------------------------------------------------
extern "C" void kernel_launch(void* const* d_in, const int* in_sizes, int n_in,
                              void* d_out, int out_size) {
    const float* x     = (const float*)d_in[0];
    const float* w     = (const float*)d_in[1];
    const float* gamma = (const float*)d_in[2];
    const float* beta  = (const float*)d_in[3];
    const float* mean  = (const float*)d_in[4];
    const float* var   = (const float*)d_in[5];
    float* out = (float*)d_out;

    prep_kernel<<<dim3(Nn / 32, Cc / 32, Bb), dim3(32, 8)>>>(x);
    sq_kernel<<<dim3(Nn / 256, Bb), 256>>>(x);

    static int smem_set = 0;
    if (!smem_set) {
        cudaFuncSetAttribute(topk1_kernel, cudaFuncAttributeMaxDynamicSharedMemorySize, SMEM_TOTAL);
        smem_set = 1;
    }
    topk1_kernel<<<dim3(Nn / 128, Bb), 256, SMEM_TOTAL>>>();
    rescore_kernel<<<dim3(Nn / 8, Bb), 256>>>();

    pw_kernel<<<dim3(Nn / 128, Bb, 2), 128>>>(x, w, gamma, beta, mean, var);
    out_kernel<<<dim3(Nn / 32, Bb), 256>>>(out);
}